// round 1
// baseline (speedup 1.0000x reference)
#include <cuda_runtime.h>
#include <math.h>

#define NB 32
#define SL 2048
#define ENC_D 1024
#define ATTN_D 1024
#define OUT_D 1024
#define MROWS (NB * SL)

// scratch (no allocations allowed)
__device__ float g_dec_h[NB * ATTN_D];   // b_enc + b_dec + dec @ W_dec
__device__ float g_scores[NB * SL];      // raw attention scores
__device__ float g_ctx[NB * ENC_D];      // context before out projection

// ---------------------------------------------------------------------------
// Kernel 1: g_dec_h[b][a] = b_enc[a] + b_dec[a] + sum_d dec[b][d] * W_dec[d][a]
// grid (ATTN_D/256, NB), block 256
// ---------------------------------------------------------------------------
__global__ void __launch_bounds__(256) k_dec(const float* __restrict__ dec,
                                             const float* __restrict__ Wd,
                                             const float* __restrict__ bd,
                                             const float* __restrict__ be) {
    __shared__ float sdec[1024];
    int b = blockIdx.y;
    for (int i = threadIdx.x; i < 1024; i += 256) sdec[i] = dec[b * 1024 + i];
    __syncthreads();
    int a = blockIdx.x * 256 + threadIdx.x;
    float acc = bd[a] + be[a];
#pragma unroll 8
    for (int d = 0; d < 1024; d++) acc += sdec[d] * Wd[d * 1024 + a];
    g_dec_h[b * ATTN_D + a] = acc;
}

// ---------------------------------------------------------------------------
// Kernel 2: fused score GEMM.
// score[m] = sum_a w_attn[a] * tanh( (enc[m,:] @ W_enc)[a] + g_dec_h[b][a] )
// BM=64 rows per block (aligned within one batch since 64 | 2048),
// loops over N in 64-col tiles, K in 16-col tiles. 4x4 per-thread micro-tile.
// ---------------------------------------------------------------------------
#define BM 64
#define BN 64
#define BK 16

__global__ void __launch_bounds__(256) k_scores(const float* __restrict__ A,
                                                const float* __restrict__ W,
                                                const float* __restrict__ wat) {
    __shared__ float sA[BK][BM];   // transposed A tile
    __shared__ float sB[BK][BN];

    int tid = threadIdx.x;
    int tx = tid & 15;        // 0..15 -> column group
    int ty = tid >> 4;        // 0..15 -> row group
    int m0 = blockIdx.x * BM;
    int b  = m0 / SL;

    const float* Ablk = A + (size_t)m0 * ENC_D;

    // global->smem load mapping
    int la_m = tid >> 2;            // 0..63 row within tile
    int la_k = (tid & 3) * 4;       // 0,4,8,12 k offset (float4)
    int lb_k = tid >> 4;            // 0..15 k row
    int lb_n = (tid & 15) * 4;      // n offset (float4)

    float sprt[4] = {0.f, 0.f, 0.f, 0.f};

    for (int nt = 0; nt < ATTN_D; nt += BN) {
        float acc[4][4] = {};
        for (int kt = 0; kt < ENC_D; kt += BK) {
            float4 av = *(const float4*)(Ablk + (size_t)la_m * ENC_D + kt + la_k);
            float4 bv = *(const float4*)(W + (size_t)(kt + lb_k) * ATTN_D + nt + lb_n);
            __syncthreads();   // previous tile fully consumed
            sA[la_k + 0][la_m] = av.x;
            sA[la_k + 1][la_m] = av.y;
            sA[la_k + 2][la_m] = av.z;
            sA[la_k + 3][la_m] = av.w;
            *(float4*)&sB[lb_k][lb_n] = bv;
            __syncthreads();
#pragma unroll
            for (int kk = 0; kk < BK; kk++) {
                float4 a4 = *(const float4*)&sA[kk][ty * 4];
                float4 b4 = *(const float4*)&sB[kk][tx * 4];
                float ar[4] = {a4.x, a4.y, a4.z, a4.w};
                float br[4] = {b4.x, b4.y, b4.z, b4.w};
#pragma unroll
                for (int i = 0; i < 4; i++)
#pragma unroll
                    for (int j = 0; j < 4; j++) acc[i][j] += ar[i] * br[j];
            }
        }
        // epilogue for this N tile: tanh + weighted reduce over columns
        int colb = nt + tx * 4;
#pragma unroll
        for (int j = 0; j < 4; j++) {
            float bdv = g_dec_h[b * ATTN_D + colb + j];
            float wv  = wat[colb + j];
#pragma unroll
            for (int i = 0; i < 4; i++)
                sprt[i] += wv * tanhf(acc[i][j] + bdv);
        }
    }

    // reduce across the 16 threads (tx) sharing each row group (width-16 shfl)
#pragma unroll
    for (int off = 8; off; off >>= 1)
#pragma unroll
        for (int i = 0; i < 4; i++)
            sprt[i] += __shfl_down_sync(0xffffffffu, sprt[i], off, 16);

    if (tx == 0) {
#pragma unroll
        for (int i = 0; i < 4; i++)
            g_scores[m0 + ty * 4 + i] = sprt[i];
    }
}

// ---------------------------------------------------------------------------
// Kernel 3: masked softmax over S per batch row. grid NB, block 256.
// Writes attn to output (zeros at masked positions).
// ---------------------------------------------------------------------------
__global__ void __launch_bounds__(256) k_softmax(const int* __restrict__ enc_len,
                                                 float* __restrict__ attn_out) {
    __shared__ float red[256];
    int b = blockIdx.x;
    int len = enc_len[b];
    const float* sc = g_scores + b * SL;
    int t = threadIdx.x;

    float m = -1e30f;
    for (int s = t; s < len; s += 256) m = fmaxf(m, sc[s]);
    red[t] = m;
    __syncthreads();
    for (int o = 128; o; o >>= 1) {
        if (t < o) red[t] = fmaxf(red[t], red[t + o]);
        __syncthreads();
    }
    m = red[0];
    __syncthreads();

    float sum = 0.f;
    for (int s = t; s < len; s += 256) sum += expf(sc[s] - m);
    red[t] = sum;
    __syncthreads();
    for (int o = 128; o; o >>= 1) {
        if (t < o) red[t] += red[t + o];
        __syncthreads();
    }
    float inv = 1.f / red[0];

    for (int s = t; s < SL; s += 256)
        attn_out[b * SL + s] = (s < len) ? expf(sc[s] - m) * inv : 0.f;
}

// ---------------------------------------------------------------------------
// Kernel 4: context[b][e] = sum_{s<len} attn[b][s] * enc[b][s][e]
// grid (ENC_D/256, NB), block 256.
// ---------------------------------------------------------------------------
__global__ void __launch_bounds__(256) k_context(const float* __restrict__ enc,
                                                 const float* __restrict__ attn,
                                                 const int* __restrict__ enc_len) {
    int b = blockIdx.y;
    int e = blockIdx.x * 256 + threadIdx.x;
    int len = enc_len[b];
    const float* eb = enc + (size_t)b * SL * ENC_D;
    const float* ab = attn + b * SL;
    float acc0 = 0.f, acc1 = 0.f, acc2 = 0.f, acc3 = 0.f;
    int s = 0;
    for (; s + 3 < len; s += 4) {
        acc0 += ab[s + 0] * eb[(size_t)(s + 0) * ENC_D + e];
        acc1 += ab[s + 1] * eb[(size_t)(s + 1) * ENC_D + e];
        acc2 += ab[s + 2] * eb[(size_t)(s + 2) * ENC_D + e];
        acc3 += ab[s + 3] * eb[(size_t)(s + 3) * ENC_D + e];
    }
    for (; s < len; s++) acc0 += ab[s] * eb[(size_t)s * ENC_D + e];
    g_ctx[b * ENC_D + e] = (acc0 + acc1) + (acc2 + acc3);
}

// ---------------------------------------------------------------------------
// Kernel 5: out[b][o] = b_out[o] + sum_e ctx[b][e] * W_out[e][o]
// ---------------------------------------------------------------------------
__global__ void __launch_bounds__(256) k_out(const float* __restrict__ Wo,
                                             const float* __restrict__ bo,
                                             float* __restrict__ out) {
    __shared__ float sctx[1024];
    int b = blockIdx.y;
    for (int i = threadIdx.x; i < 1024; i += 256) sctx[i] = g_ctx[b * 1024 + i];
    __syncthreads();
    int o = blockIdx.x * 256 + threadIdx.x;
    float acc = bo[o];
#pragma unroll 8
    for (int e = 0; e < 1024; e++) acc += sctx[e] * Wo[e * 1024 + o];
    out[b * OUT_D + o] = acc;
}

// ---------------------------------------------------------------------------
extern "C" void kernel_launch(void* const* d_in, const int* in_sizes, int n_in,
                              void* d_out, int out_size) {
    const float* enc     = (const float*)d_in[0];
    const float* dec     = (const float*)d_in[1];
    const float* W_enc   = (const float*)d_in[2];
    const float* b_enc   = (const float*)d_in[3];
    const float* W_dec   = (const float*)d_in[4];
    const float* b_dec   = (const float*)d_in[5];
    const float* w_attn  = (const float*)d_in[6];
    const float* W_out   = (const float*)d_in[7];
    const float* b_out   = (const float*)d_in[8];
    const int*   enc_len = (const int*)d_in[9];

    float* out      = (float*)d_out;
    float* ctx_out  = out;                 // [NB, OUT_D]
    float* attn_out = out + NB * OUT_D;    // [NB, SL]

    k_dec<<<dim3(ATTN_D / 256, NB), 256>>>(dec, W_dec, b_dec, b_enc);
    k_scores<<<MROWS / BM, 256>>>(enc, W_enc, w_attn);
    k_softmax<<<NB, 256>>>(enc_len, attn_out);
    k_context<<<dim3(ENC_D / 256, NB), 256>>>(enc, attn_out, enc_len);
    k_out<<<dim3(OUT_D / 256, NB), 256>>>(W_out, b_out, ctx_out);
}

// round 4
// speedup vs baseline: 3.0854x; 3.0854x over previous
#include <cuda_runtime.h>
#include <math.h>

#define NB 32
#define SL 2048
#define ENC_D 1024
#define ATTN_D 1024
#define OUT_D 1024
#define MROWS (NB * SL)
#define SCH 8            // s-chunks for context partials
#define CS (SL / SCH)    // 256

// scratch (no allocations allowed)
__device__ float g_dec_h[NB * ATTN_D];        // b_enc + b_dec + dec @ W_dec
__device__ float g_scores[NB * SL];           // raw attention scores
__device__ float g_ctxp[SCH][NB * ENC_D];     // context partials per s-chunk

__device__ __forceinline__ unsigned f2tf(float f) {
    unsigned u;
    asm("cvt.rna.tf32.f32 %0, %1;" : "=r"(u) : "f"(f));
    return u;
}

// ---------------------------------------------------------------------------
// Kernel 1: g_dec_h[b][a] = b_enc[a] + b_dec[a] + sum_d dec[b][d] * W_dec[d][a]
// ---------------------------------------------------------------------------
__global__ void __launch_bounds__(256) k_dec(const float* __restrict__ dec,
                                             const float* __restrict__ Wd,
                                             const float* __restrict__ bd,
                                             const float* __restrict__ be) {
    __shared__ float sdec[1024];
    int b = blockIdx.y;
    for (int i = threadIdx.x; i < 1024; i += 256) sdec[i] = dec[b * 1024 + i];
    __syncthreads();
    int a = blockIdx.x * 256 + threadIdx.x;
    float acc = bd[a] + be[a];
#pragma unroll 8
    for (int d = 0; d < 1024; d++) acc += sdec[d] * Wd[d * 1024 + a];
    g_dec_h[b * ATTN_D + a] = acc;
}

// ---------------------------------------------------------------------------
// Kernel 2: fused score GEMM on tf32 tensor cores.
// score[m] = sum_a w_attn[a] * tanh( (enc[m,:] @ W_enc)[a] + dec_h[b][a] )
// BM=128 rows/block, BN=128 col tiles, BK=32. 8 warps: 4 (M) x 2 (N),
// warp tile 32x64, mma.m16n8k8 tf32.
// ---------------------------------------------------------------------------
#define BM 128
#define BN 128
#define BK 32
#define SPAD 136   // smem row stride (floats): frag-load banks = tig*8+g, conflict-free

__global__ void __launch_bounds__(256, 2) k_scores(const float* __restrict__ A,
                                                   const float* __restrict__ W,
                                                   const float* __restrict__ wat) {
    __shared__ unsigned sA[BK][SPAD];  // [k][m]
    __shared__ unsigned sB[BK][SPAD];  // [k][n]
    __shared__ float sdec[ATTN_D];
    __shared__ float swv[ATTN_D];
    __shared__ float sred[BM][2];

    int tid  = threadIdx.x;
    int lane = tid & 31, warp = tid >> 5;
    int wm = warp & 3, wn = warp >> 2;   // warp grid 4 (M) x 2 (N)
    int g = lane >> 2, tig = lane & 3;

    int m0 = blockIdx.x * BM;
    int b  = m0 / SL;

    for (int i = tid; i < ATTN_D; i += 256) {
        sdec[i] = g_dec_h[b * ATTN_D + i];
        swv[i]  = wat[i];
    }

    // global load mappings
    int am = tid >> 1;                 // 0..127 (A row within tile)
    int ak = (tid & 1) * 4;            // + q*8  (A k offset)
    int bk = tid >> 3;                 // 0..31  (B k row)
    int bn = (tid & 7) * 4;            // + q*32 (B n offset)
    const float* Arow = A + (size_t)(m0 + am) * ENC_D;

    float sprt[4] = {0.f, 0.f, 0.f, 0.f};  // row = g + 8*idx (within warp 32-row tile)

    for (int nt = 0; nt < ATTN_D; nt += BN) {
        float acc[2][8][4];
#pragma unroll
        for (int i = 0; i < 2; i++)
#pragma unroll
            for (int j = 0; j < 8; j++)
#pragma unroll
                for (int c = 0; c < 4; c++) acc[i][j][c] = 0.f;

        float4 ra[4], rb[4];
#pragma unroll
        for (int q = 0; q < 4; q++) {
            ra[q] = *(const float4*)(Arow + ak + q * 8);
            rb[q] = *(const float4*)(W + (size_t)bk * ATTN_D + nt + bn + q * 32);
        }

        for (int kt = 0; kt < ENC_D / BK; kt++) {
            __syncthreads();
#pragma unroll
            for (int q = 0; q < 4; q++) {
                sA[ak + q * 8 + 0][am] = f2tf(ra[q].x);
                sA[ak + q * 8 + 1][am] = f2tf(ra[q].y);
                sA[ak + q * 8 + 2][am] = f2tf(ra[q].z);
                sA[ak + q * 8 + 3][am] = f2tf(ra[q].w);
                uint4 bv;
                bv.x = f2tf(rb[q].x); bv.y = f2tf(rb[q].y);
                bv.z = f2tf(rb[q].z); bv.w = f2tf(rb[q].w);
                *(uint4*)&sB[bk][bn + q * 32] = bv;
            }
            __syncthreads();

            if (kt + 1 < ENC_D / BK) {
                int kn = (kt + 1) * BK;
#pragma unroll
                for (int q = 0; q < 4; q++) {
                    ra[q] = *(const float4*)(Arow + kn + ak + q * 8);
                    rb[q] = *(const float4*)(W + (size_t)(kn + bk) * ATTN_D + nt + bn + q * 32);
                }
            }

#pragma unroll
            for (int ks = 0; ks < 4; ks++) {
                int kk = ks * 8;
                unsigned af[2][4], bf[8][2];
#pragma unroll
                for (int i = 0; i < 2; i++) {
                    int mr = wm * 32 + 16 * i + g;
                    af[i][0] = sA[kk + tig    ][mr];
                    af[i][1] = sA[kk + tig    ][mr + 8];
                    af[i][2] = sA[kk + tig + 4][mr];
                    af[i][3] = sA[kk + tig + 4][mr + 8];
                }
#pragma unroll
                for (int j = 0; j < 8; j++) {
                    int nc = wn * 64 + j * 8 + g;
                    bf[j][0] = sB[kk + tig    ][nc];
                    bf[j][1] = sB[kk + tig + 4][nc];
                }
#pragma unroll
                for (int i = 0; i < 2; i++)
#pragma unroll
                    for (int j = 0; j < 8; j++) {
                        asm volatile(
                            "mma.sync.aligned.m16n8k8.row.col.f32.tf32.tf32.f32 "
                            "{%0,%1,%2,%3}, {%4,%5,%6,%7}, {%8,%9}, {%0,%1,%2,%3};"
                            : "+f"(acc[i][j][0]), "+f"(acc[i][j][1]),
                              "+f"(acc[i][j][2]), "+f"(acc[i][j][3])
                            : "r"(af[i][0]), "r"(af[i][1]), "r"(af[i][2]), "r"(af[i][3]),
                              "r"(bf[j][0]), "r"(bf[j][1]));
                    }
            }
        }

        // epilogue: tanh + w-weighted column reduce for this N tile
#pragma unroll
        for (int i = 0; i < 2; i++)
#pragma unroll
            for (int j = 0; j < 8; j++) {
                int c0 = nt + wn * 64 + j * 8 + 2 * tig;
                float d0 = sdec[c0], d1 = sdec[c0 + 1];
                float w0 = swv[c0],  w1 = swv[c0 + 1];
                sprt[2 * i + 0] += w0 * tanhf(acc[i][j][0] + d0) + w1 * tanhf(acc[i][j][1] + d1);
                sprt[2 * i + 1] += w0 * tanhf(acc[i][j][2] + d0) + w1 * tanhf(acc[i][j][3] + d1);
            }
    }

    // reduce over the 4 lanes of each quad (they share the same rows)
#pragma unroll
    for (int off = 2; off; off >>= 1)
#pragma unroll
        for (int r = 0; r < 4; r++)
            sprt[r] += __shfl_down_sync(0xffffffffu, sprt[r], off, 4);

    if (tig == 0) {
#pragma unroll
        for (int r = 0; r < 4; r++)
            sred[wm * 32 + g + 8 * r][wn] = sprt[r];
    }
    __syncthreads();
    if (tid < BM)
        g_scores[m0 + tid] = sred[tid][0] + sred[tid][1];
}

// ---------------------------------------------------------------------------
// Kernel 3: masked softmax over S per batch row. grid NB, block 256.
// ---------------------------------------------------------------------------
__global__ void __launch_bounds__(256) k_softmax(const int* __restrict__ enc_len,
                                                 float* __restrict__ attn_out) {
    __shared__ float red[256];
    int b = blockIdx.x;
    int len = enc_len[b];
    const float* sc = g_scores + b * SL;
    int t = threadIdx.x;

    float m = -1e30f;
    for (int s = t; s < len; s += 256) m = fmaxf(m, sc[s]);
    red[t] = m;
    __syncthreads();
    for (int o = 128; o; o >>= 1) {
        if (t < o) red[t] = fmaxf(red[t], red[t + o]);
        __syncthreads();
    }
    m = red[0];
    __syncthreads();

    float sum = 0.f;
    for (int s = t; s < len; s += 256) sum += expf(sc[s] - m);
    red[t] = sum;
    __syncthreads();
    for (int o = 128; o; o >>= 1) {
        if (t < o) red[t] += red[t + o];
        __syncthreads();
    }
    float inv = 1.f / red[0];

    for (int s = t; s < SL; s += 256)
        attn_out[b * SL + s] = (s < len) ? expf(sc[s] - m) * inv : 0.f;
}

// ---------------------------------------------------------------------------
// Kernel 4: context partials. attn is exactly 0 beyond len, so no masking.
// grid (ENC_D/256, NB, SCH), block 256.
// ---------------------------------------------------------------------------
__global__ void __launch_bounds__(256) k_context(const float* __restrict__ enc,
                                                 const float* __restrict__ attn) {
    __shared__ float sat[CS];
    int b = blockIdx.y, ch = blockIdx.z;
    int e = blockIdx.x * 256 + threadIdx.x;
    int s0 = ch * CS;

    for (int i = threadIdx.x; i < CS; i += 256) sat[i] = attn[b * SL + s0 + i];
    __syncthreads();

    const float* eb = enc + ((size_t)b * SL + s0) * ENC_D + e;
    float a0 = 0.f, a1 = 0.f, a2 = 0.f, a3 = 0.f;
#pragma unroll 4
    for (int s = 0; s < CS; s += 4) {
        a0 += sat[s + 0] * eb[(size_t)(s + 0) * ENC_D];
        a1 += sat[s + 1] * eb[(size_t)(s + 1) * ENC_D];
        a2 += sat[s + 2] * eb[(size_t)(s + 2) * ENC_D];
        a3 += sat[s + 3] * eb[(size_t)(s + 3) * ENC_D];
    }
    g_ctxp[ch][b * ENC_D + e] = (a0 + a1) + (a2 + a3);
}

// ---------------------------------------------------------------------------
// Kernel 5: out[b][o] = b_out[o] + sum_e (sum_p ctxp[p][b][e]) * W_out[e][o]
// ---------------------------------------------------------------------------
__global__ void __launch_bounds__(256) k_out(const float* __restrict__ Wo,
                                             const float* __restrict__ bo,
                                             float* __restrict__ out) {
    __shared__ float sctx[1024];
    int b = blockIdx.y;
    for (int i = threadIdx.x; i < 1024; i += 256) {
        float v = 0.f;
#pragma unroll
        for (int p = 0; p < SCH; p++) v += g_ctxp[p][b * ENC_D + i];
        sctx[i] = v;
    }
    __syncthreads();
    int o = blockIdx.x * 256 + threadIdx.x;
    float acc = bo[o];
#pragma unroll 8
    for (int e = 0; e < 1024; e++) acc += sctx[e] * Wo[e * 1024 + o];
    out[b * OUT_D + o] = acc;
}

// ---------------------------------------------------------------------------
extern "C" void kernel_launch(void* const* d_in, const int* in_sizes, int n_in,
                              void* d_out, int out_size) {
    const float* enc     = (const float*)d_in[0];
    const float* dec     = (const float*)d_in[1];
    const float* W_enc   = (const float*)d_in[2];
    const float* b_enc   = (const float*)d_in[3];
    const float* W_dec   = (const float*)d_in[4];
    const float* b_dec   = (const float*)d_in[5];
    const float* w_attn  = (const float*)d_in[6];
    const float* W_out   = (const float*)d_in[7];
    const float* b_out   = (const float*)d_in[8];
    const int*   enc_len = (const int*)d_in[9];

    float* out      = (float*)d_out;
    float* ctx_out  = out;                 // [NB, OUT_D]
    float* attn_out = out + NB * OUT_D;    // [NB, SL]

    k_dec<<<dim3(ATTN_D / 256, NB), 256>>>(dec, W_dec, b_dec, b_enc);
    k_scores<<<MROWS / BM, 256>>>(enc, W_enc, w_attn);
    k_softmax<<<NB, 256>>>(enc_len, attn_out);
    k_context<<<dim3(ENC_D / 256, NB, SCH), 256>>>(enc, attn_out);
    k_out<<<dim3(OUT_D / 256, NB), 256>>>(W_out, b_out, ctx_out);
}

// round 6
// speedup vs baseline: 3.9755x; 1.2885x over previous
#include <cuda_runtime.h>
#include <math.h>

#define NB 32
#define SL 2048
#define ENC_D 1024
#define ATTN_D 1024
#define OUT_D 1024
#define MROWS (NB * SL)
#define SCH 8            // s-chunks for context partials
#define CS (SL / SCH)    // 256
#define NT_TILES 8

#define BM 128
#define BN 128
#define BK 32

// dynamic smem word-layout (floats):
//  SA: [0, 8192)      stage s at s*4096; elem (r,k): r*32 + (((k>>2)^(r&7))<<2) + (k&3)
//  SB: [8192, 16384)  stage s at 8192+s*4096; elem (k,n): k*128 + (((n>>2)^((k&3)<<1))<<2) + (n&3)
//  sdec: [16384,16512)  swv: [16512,16640)  sred: [16640,16896)
#define SMEM_WORDS 16896
#define SMEM_BYTES (SMEM_WORDS * 4)

// scratch (no allocations allowed)
__device__ float g_dec_h[NB * ATTN_D];          // b_enc + b_dec + dec @ W_dec
__device__ float g_scp[NT_TILES][MROWS];        // score partials per nt tile
__device__ float g_ctxp[SCH][NB * ENC_D];       // context partials per s-chunk
__device__ float g_Wtf[ENC_D * ATTN_D];         // W_enc pre-rounded to tf32 (rna)

__device__ __forceinline__ unsigned f2tf(float f) {
    unsigned u;
    asm("cvt.rna.tf32.f32 %0, %1;" : "=r"(u) : "f"(f));
    return u;
}
__device__ __forceinline__ float tanhfast(float x) {
    float y;
    asm("tanh.approx.f32 %0, %1;" : "=f"(y) : "f"(x));
    return y;
}
__device__ __forceinline__ void cpa16(unsigned saddr, const float* g) {
    asm volatile("cp.async.cg.shared.global [%0], [%1], 16;" :: "r"(saddr), "l"(g));
}

// ---------------------------------------------------------------------------
// Kernel 0: pre-round W_enc to tf32
// ---------------------------------------------------------------------------
__global__ void __launch_bounds__(256) k_prep(const float* __restrict__ W) {
    int i = blockIdx.x * 256 + threadIdx.x;
    ((unsigned*)g_Wtf)[i] = f2tf(W[i]);
}

// ---------------------------------------------------------------------------
// Kernel 1: g_dec_h[b][a] = b_enc[a] + b_dec[a] + sum_d dec[b][d] * W_dec[d][a]
// ---------------------------------------------------------------------------
__global__ void __launch_bounds__(256) k_dec(const float* __restrict__ dec,
                                             const float* __restrict__ Wd,
                                             const float* __restrict__ bd,
                                             const float* __restrict__ be) {
    __shared__ float sdec[1024];
    int b = blockIdx.y;
    for (int i = threadIdx.x; i < 1024; i += 256) sdec[i] = dec[b * 1024 + i];
    __syncthreads();
    int a = blockIdx.x * 256 + threadIdx.x;
    float acc = bd[a] + be[a];
#pragma unroll 8
    for (int d = 0; d < 1024; d++) acc += sdec[d] * Wd[d * 1024 + a];
    g_dec_h[b * ATTN_D + a] = acc;
}

// ---------------------------------------------------------------------------
// Kernel 2: fused score GEMM, tf32 mma + cp.async 2-stage pipeline.
// grid 4096: bid = mb*8 + ntb. Each CTA: one (128-row, 128-col) tile, K=1024.
// partial score (over its 128 cols) -> g_scp[ntb][m].
// ---------------------------------------------------------------------------
__global__ void __launch_bounds__(256, 2) k_scores(const float* __restrict__ A,
                                                   const float* __restrict__ wat) {
    extern __shared__ float dsm[];
    unsigned* dsu = (unsigned*)dsm;

    const int tid  = threadIdx.x;
    const int lane = tid & 31, warp = tid >> 5;
    const int wm = warp & 3, wn = warp >> 2;     // 4 (M) x 2 (N)
    const int g = lane >> 2, tig = lane & 3;

    const int mb = blockIdx.x >> 3, ntb = blockIdx.x & 7;
    const int m0 = mb * BM, nt = ntb * BN;
    const int b  = m0 / SL;

    if (tid < 128) {
        dsm[16384 + tid] = g_dec_h[b * ATTN_D + nt + tid];
        dsm[16512 + tid] = wat[nt + tid];
    }

    // cp.async mappings
    const int ar = tid >> 1;             // A row 0..127
    const int aq = (tid & 1) * 4;        // A chunk base (of 8 per row)
    const float* gA = A + (size_t)(m0 + ar) * ENC_D + aq * 4;
    const int br = tid >> 3;             // B k-row 0..31
    const int bq = (tid & 7) * 4;        // B chunk base (of 32 per row)
    const float* gB = g_Wtf + (size_t)br * ATTN_D + nt + bq * 4;

    const unsigned smem0 = (unsigned)__cvta_generic_to_shared(dsm);
    // precompute swizzled store byte-offsets
    unsigned sa_off[4], sb_off[4];
#pragma unroll
    for (int c = 0; c < 4; c++) {
        sa_off[c] = (ar * 32 + (((aq + c) ^ (ar & 7)) << 2)) * 4;
        sb_off[c] = (8192 + br * 128 + (((bq + c) ^ ((br & 3) << 1)) << 2)) * 4;
    }

    float acc[2][8][4];
#pragma unroll
    for (int i = 0; i < 2; i++)
#pragma unroll
        for (int j = 0; j < 8; j++)
#pragma unroll
            for (int c = 0; c < 4; c++) acc[i][j][c] = 0.f;

    // prologue: stage 0, kt=0
    {
        const float* ga = gA;
        const float* gb = gB;
#pragma unroll
        for (int c = 0; c < 4; c++) cpa16(smem0 + sa_off[c], ga + c * 4);
#pragma unroll
        for (int c = 0; c < 4; c++) cpa16(smem0 + sb_off[c], gb + c * 4);
        asm volatile("cp.async.commit_group;");
    }

    for (int kt = 0; kt < 32; kt++) {
        const int s = kt & 1;
        if (kt < 31) {
            const unsigned stoff = ((s ^ 1) * 4096) * 4;
            const float* ga = gA + (kt + 1) * 32;
            const float* gb = gB + (size_t)(kt + 1) * 32 * ATTN_D;
#pragma unroll
            for (int c = 0; c < 4; c++) cpa16(smem0 + stoff + sa_off[c], ga + c * 4);
#pragma unroll
            for (int c = 0; c < 4; c++) cpa16(smem0 + stoff + sb_off[c], gb + c * 4);
            asm volatile("cp.async.commit_group;");
            asm volatile("cp.async.wait_group 1;");
        } else {
            asm volatile("cp.async.wait_group 0;");
        }
        __syncthreads();

        // compute on stage s: 4 ks-steps of k8
        const int sa = s * 4096;
        const int sb = 8192 + s * 4096;
#pragma unroll
        for (int ks = 0; ks < 4; ks++) {
            unsigned af[2][4];
#pragma unroll
            for (int i = 0; i < 2; i++) {
                const int mr = wm * 32 + 16 * i + g;
                const int base = sa + mr * 32;
                const int x0 = (((2 * ks)     ^ g) << 2) + tig;
                const int x1 = (((2 * ks + 1) ^ g) << 2) + tig;
                af[i][0] = dsu[base + x0];
                af[i][1] = dsu[base + 256 + x0];
                af[i][2] = dsu[base + x1];
                af[i][3] = dsu[base + 256 + x1];
            }
            unsigned bf[8][2];
#pragma unroll
            for (int j = 0; j < 8; j++) {
                const int nc = wn * 64 + j * 8 + g;
                const int col = ((((nc >> 2) ^ (tig << 1))) << 2) + (nc & 3);
                const int base = sb + (ks * 8 + tig) * 128;
                bf[j][0] = dsu[base + col];
                bf[j][1] = dsu[base + 512 + col];
            }
#pragma unroll
            for (int i = 0; i < 2; i++)
#pragma unroll
                for (int j = 0; j < 8; j++) {
                    asm volatile(
                        "mma.sync.aligned.m16n8k8.row.col.f32.tf32.tf32.f32 "
                        "{%0,%1,%2,%3}, {%4,%5,%6,%7}, {%8,%9}, {%0,%1,%2,%3};"
                        : "+f"(acc[i][j][0]), "+f"(acc[i][j][1]),
                          "+f"(acc[i][j][2]), "+f"(acc[i][j][3])
                        : "r"(af[i][0]), "r"(af[i][1]), "r"(af[i][2]), "r"(af[i][3]),
                          "r"(bf[j][0]), "r"(bf[j][1]));
                }
        }
        __syncthreads();
    }

    // epilogue: tanh + w-weighted column reduce (local 128 cols)
    float sprt[4] = {0.f, 0.f, 0.f, 0.f};
#pragma unroll
    for (int i = 0; i < 2; i++)
#pragma unroll
        for (int j = 0; j < 8; j++) {
            const int c0 = wn * 64 + j * 8 + 2 * tig;
            const float d0 = dsm[16384 + c0], d1 = dsm[16384 + c0 + 1];
            const float w0 = dsm[16512 + c0], w1 = dsm[16512 + c0 + 1];
            sprt[2 * i + 0] += w0 * tanhfast(acc[i][j][0] + d0) + w1 * tanhfast(acc[i][j][1] + d1);
            sprt[2 * i + 1] += w0 * tanhfast(acc[i][j][2] + d0) + w1 * tanhfast(acc[i][j][3] + d1);
        }

#pragma unroll
    for (int off = 2; off; off >>= 1)
#pragma unroll
        for (int r = 0; r < 4; r++)
            sprt[r] += __shfl_down_sync(0xffffffffu, sprt[r], off, 4);

    if (tig == 0) {
#pragma unroll
        for (int r = 0; r < 4; r++)
            dsm[16640 + (wm * 32 + g + 8 * r) * 2 + wn] = sprt[r];
    }
    __syncthreads();
    if (tid < BM)
        g_scp[ntb][m0 + tid] = dsm[16640 + tid * 2] + dsm[16640 + tid * 2 + 1];
}

// ---------------------------------------------------------------------------
// Kernel 3: sum partials + masked softmax over S per batch row. grid NB.
// ---------------------------------------------------------------------------
__global__ void __launch_bounds__(256) k_softmax(const int* __restrict__ enc_len,
                                                 float* __restrict__ attn_out) {
    __shared__ float ssc[SL];
    __shared__ float red[256];
    int b = blockIdx.x;
    int len = enc_len[b];
    int t = threadIdx.x;

    for (int s = t; s < SL; s += 256) {
        float v = 0.f;
#pragma unroll
        for (int p = 0; p < NT_TILES; p++) v += g_scp[p][b * SL + s];
        ssc[s] = v;
    }
    __syncthreads();

    float m = -1e30f;
    for (int s = t; s < len; s += 256) m = fmaxf(m, ssc[s]);
    red[t] = m;
    __syncthreads();
    for (int o = 128; o; o >>= 1) {
        if (t < o) red[t] = fmaxf(red[t], red[t + o]);
        __syncthreads();
    }
    m = red[0];
    __syncthreads();

    float sum = 0.f;
    for (int s = t; s < len; s += 256) sum += expf(ssc[s] - m);
    red[t] = sum;
    __syncthreads();
    for (int o = 128; o; o >>= 1) {
        if (t < o) red[t] += red[t + o];
        __syncthreads();
    }
    float inv = 1.f / red[0];

    for (int s = t; s < SL; s += 256)
        attn_out[b * SL + s] = (s < len) ? expf(ssc[s] - m) * inv : 0.f;
}

// ---------------------------------------------------------------------------
// Kernel 4: context partials. attn is exactly 0 beyond len, so no masking.
// ---------------------------------------------------------------------------
__global__ void __launch_bounds__(256) k_context(const float* __restrict__ enc,
                                                 const float* __restrict__ attn) {
    __shared__ float sat[CS];
    int b = blockIdx.y, ch = blockIdx.z;
    int e = blockIdx.x * 256 + threadIdx.x;
    int s0 = ch * CS;

    for (int i = threadIdx.x; i < CS; i += 256) sat[i] = attn[b * SL + s0 + i];
    __syncthreads();

    const float* eb = enc + ((size_t)b * SL + s0) * ENC_D + e;
    float a0 = 0.f, a1 = 0.f, a2 = 0.f, a3 = 0.f;
#pragma unroll 4
    for (int s = 0; s < CS; s += 4) {
        a0 += sat[s + 0] * eb[(size_t)(s + 0) * ENC_D];
        a1 += sat[s + 1] * eb[(size_t)(s + 1) * ENC_D];
        a2 += sat[s + 2] * eb[(size_t)(s + 2) * ENC_D];
        a3 += sat[s + 3] * eb[(size_t)(s + 3) * ENC_D];
    }
    g_ctxp[ch][b * ENC_D + e] = (a0 + a1) + (a2 + a3);
}

// ---------------------------------------------------------------------------
// Kernel 5: out[b][o] = b_out[o] + sum_e (sum_p ctxp[p][b][e]) * W_out[e][o]
// ---------------------------------------------------------------------------
__global__ void __launch_bounds__(256) k_out(const float* __restrict__ Wo,
                                             const float* __restrict__ bo,
                                             float* __restrict__ out) {
    __shared__ float sctx[1024];
    int b = blockIdx.y;
    for (int i = threadIdx.x; i < 1024; i += 256) {
        float v = 0.f;
#pragma unroll
        for (int p = 0; p < SCH; p++) v += g_ctxp[p][b * ENC_D + i];
        sctx[i] = v;
    }
    __syncthreads();
    int o = blockIdx.x * 256 + threadIdx.x;
    float acc = bo[o];
#pragma unroll 8
    for (int e = 0; e < 1024; e++) acc += sctx[e] * Wo[e * 1024 + o];
    out[b * OUT_D + o] = acc;
}

// ---------------------------------------------------------------------------
extern "C" void kernel_launch(void* const* d_in, const int* in_sizes, int n_in,
                              void* d_out, int out_size) {
    const float* enc     = (const float*)d_in[0];
    const float* dec     = (const float*)d_in[1];
    const float* W_enc   = (const float*)d_in[2];
    const float* b_enc   = (const float*)d_in[3];
    const float* W_dec   = (const float*)d_in[4];
    const float* b_dec   = (const float*)d_in[5];
    const float* w_attn  = (const float*)d_in[6];
    const float* W_out   = (const float*)d_in[7];
    const float* b_out   = (const float*)d_in[8];
    const int*   enc_len = (const int*)d_in[9];

    float* out      = (float*)d_out;
    float* ctx_out  = out;                 // [NB, OUT_D]
    float* attn_out = out + NB * OUT_D;    // [NB, SL]

    cudaFuncSetAttribute(k_scores, cudaFuncAttributeMaxDynamicSharedMemorySize,
                         SMEM_BYTES);

    k_prep<<<ENC_D * ATTN_D / 256, 256>>>(W_enc);
    k_dec<<<dim3(ATTN_D / 256, NB), 256>>>(dec, W_dec, b_dec, b_enc);
    k_scores<<<(MROWS / BM) * NT_TILES, 256, SMEM_BYTES>>>(enc, w_attn);
    k_softmax<<<NB, 256>>>(enc_len, attn_out);
    k_context<<<dim3(ENC_D / 256, NB, SCH), 256>>>(enc, attn_out);
    k_out<<<dim3(OUT_D / 256, NB), 256>>>(W_out, b_out, ctx_out);
}

// round 16
// speedup vs baseline: 5.2926x; 1.3313x over previous
#include <cuda_runtime.h>
#include <cuda_fp16.h>
#include <math.h>
#include <stdint.h>

#define NB 32
#define SL 2048
#define ENC_D 1024
#define ATTN_D 1024
#define OUT_D 1024
#define MROWS (NB * SL)
#define SCH 8            // s-chunks for context partials
#define CS (SL / SCH)    // 256
#define NT_TILES 8

#define BM 128
#define BN 128
#define BK 32
#define KP (BK / 2)      // 16 kpairs per kt chunk
#define SPAD 136         // smem row stride (u32): frag banks = 8*tig+g, conflict-free

// scratch (no allocations allowed)
__device__ float g_dec_h[NB * ATTN_D];          // b_enc + b_dec + dec @ W_dec
__device__ float g_scp[NT_TILES][MROWS];        // score partials per nt tile
__device__ float g_ctxp[SCH][NB * ENC_D];       // context partials per s-chunk
__device__ unsigned g_Whp[(ENC_D / 2) * ATTN_D];// W_enc packed half2: [kp][n] = {W[2kp][n], W[2kp+1][n]}

__device__ __forceinline__ float tanhfast(float x) {
    float y;
    asm("tanh.approx.f32 %0, %1;" : "=f"(y) : "f"(x));
    return y;
}
__device__ __forceinline__ void cpa16(unsigned saddr, const void* g) {
    asm volatile("cp.async.cg.shared.global [%0], [%1], 16;" :: "r"(saddr), "l"(g));
}
__device__ __forceinline__ unsigned packh2(float a, float b) {
    __half2 h = __floats2half2_rn(a, b);
    return *(unsigned*)&h;
}

// ---------------------------------------------------------------------------
// Kernel 0: pack W_enc (fp32 [k][n]) into half2 pairs along k: g_Whp[kp][n]
// ---------------------------------------------------------------------------
__global__ void __launch_bounds__(256) k_prep(const float* __restrict__ W) {
    int idx = blockIdx.x * 256 + threadIdx.x;        // 0 .. 512*1024-1
    int kp = idx >> 10, n = idx & 1023;
    float f0 = W[(size_t)(2 * kp) * ATTN_D + n];
    float f1 = W[(size_t)(2 * kp + 1) * ATTN_D + n];
    g_Whp[idx] = packh2(f0, f1);
}

// ---------------------------------------------------------------------------
// Kernel 1: g_dec_h[b][a] = b_enc[a] + b_dec[a] + sum_d dec[b][d] * W_dec[d][a]
// ---------------------------------------------------------------------------
__global__ void __launch_bounds__(256) k_dec(const float* __restrict__ dec,
                                             const float* __restrict__ Wd,
                                             const float* __restrict__ bd,
                                             const float* __restrict__ be) {
    __shared__ float sdec[1024];
    int b = blockIdx.y;
    for (int i = threadIdx.x; i < 1024; i += 256) sdec[i] = dec[b * 1024 + i];
    __syncthreads();
    int a = blockIdx.x * 256 + threadIdx.x;
    float acc = bd[a] + be[a];
#pragma unroll 8
    for (int d = 0; d < 1024; d++) acc += sdec[d] * Wd[d * 1024 + a];
    g_dec_h[b * ATTN_D + a] = acc;
}

// ---------------------------------------------------------------------------
// Kernel 2: fused score GEMM, fp16 mma.sync m16n8k16 + cp.async for B.
// grid 4096: bid = mb*8 + ntb. Tile 128x128, K=1024 in 32-wide chunks.
// smem: sA/sB [stage][kpair][SPAD] of half2-u32.
// A path: LDG fp32 prefetch -> cvt half2 -> STS. B path: cp.async from g_Whp.
// ---------------------------------------------------------------------------
__global__ void __launch_bounds__(256, 2) k_scores(const float* __restrict__ A,
                                                   const float* __restrict__ wat) {
    __shared__ unsigned sA[2][KP][SPAD];
    __shared__ unsigned sB[2][KP][SPAD];
    __shared__ float sdec[BN];
    __shared__ float swv[BN];
    __shared__ float sred[BM][2];

    const int tid  = threadIdx.x;
    const int lane = tid & 31, warp = tid >> 5;
    const int wm = warp & 3, wn = warp >> 2;     // 4 (M) x 2 (N)
    const int g = lane >> 2, tig = lane & 3;

    const int mb = blockIdx.x >> 3, ntb = blockIdx.x & 7;
    const int m0 = mb * BM, nt = ntb * BN;
    const int b  = m0 / SL;

    if (tid < BN) {
        sdec[tid] = g_dec_h[b * ATTN_D + nt + tid];
        swv[tid]  = wat[nt + tid];
    }

    // A mapping: row am = tid>>1, 16 k's at (tid&1)*16; 8 half2 to kpairs akp..akp+7
    const int am  = tid >> 1;
    const int ak  = (tid & 1) * 16;
    const int akp = (tid & 1) * 8;
    const float* gA = A + (size_t)(m0 + am) * ENC_D + ak;

    // B mapping: 2 chunks/thread: (kpl, nch) and (kpl+8, nch)
    const int kpl = tid >> 5;        // 0..7
    const int nch = tid & 31;        // 0..31
    const unsigned* gB = g_Whp + (size_t)kpl * ATTN_D + nt + nch * 4;

    unsigned sB_base = (unsigned)__cvta_generic_to_shared(&sB[0][0][0]);
    const unsigned sb_off0 = (kpl * SPAD + nch * 4) * 4;
    const unsigned sb_off1 = ((kpl + 8) * SPAD + nch * 4) * 4;
    const unsigned sb_stage = KP * SPAD * 4;

    float acc[2][8][4];
#pragma unroll
    for (int i = 0; i < 2; i++)
#pragma unroll
        for (int j = 0; j < 8; j++)
#pragma unroll
            for (int c = 0; c < 4; c++) acc[i][j][c] = 0.f;

    float4 ra[4];
    // prologue: kt=0 into stage 0
#pragma unroll
    for (int q = 0; q < 4; q++) ra[q] = *(const float4*)(gA + q * 4);
    cpa16(sB_base + sb_off0, gB);
    cpa16(sB_base + sb_off1, gB + (size_t)8 * ATTN_D);
    asm volatile("cp.async.commit_group;");
#pragma unroll
    for (int q = 0; q < 4; q++) {
        sA[0][akp + 2 * q + 0][am] = packh2(ra[q].x, ra[q].y);
        sA[0][akp + 2 * q + 1][am] = packh2(ra[q].z, ra[q].w);
    }

    for (int kt = 0; kt < ENC_D / BK; kt++) {
        const int s = kt & 1;
        if (kt < 31) {
#pragma unroll
            for (int q = 0; q < 4; q++)
                ra[q] = *(const float4*)(gA + (kt + 1) * BK + q * 4);
            const unsigned* gb = gB + (size_t)(kt + 1) * KP * ATTN_D;
            const unsigned dst = sB_base + (s ^ 1) * sb_stage;
            cpa16(dst + sb_off0, gb);
            cpa16(dst + sb_off1, gb + (size_t)8 * ATTN_D);
            asm volatile("cp.async.commit_group;");
            asm volatile("cp.async.wait_group 1;");
        } else {
            asm volatile("cp.async.wait_group 0;");
        }
        __syncthreads();

        // compute on stage s: 2 k16 steps
#pragma unroll
        for (int ks = 0; ks < 2; ks++) {
            const int base = ks * 8;
            unsigned af[2][4];
#pragma unroll
            for (int i = 0; i < 2; i++) {
                const int mr = wm * 32 + 16 * i + g;
                af[i][0] = sA[s][base + tig    ][mr];
                af[i][1] = sA[s][base + tig    ][mr + 8];
                af[i][2] = sA[s][base + tig + 4][mr];
                af[i][3] = sA[s][base + tig + 4][mr + 8];
            }
            unsigned bf[8][2];
#pragma unroll
            for (int j = 0; j < 8; j++) {
                const int nc = wn * 64 + j * 8 + g;
                bf[j][0] = sB[s][base + tig    ][nc];
                bf[j][1] = sB[s][base + tig + 4][nc];
            }
#pragma unroll
            for (int i = 0; i < 2; i++)
#pragma unroll
                for (int j = 0; j < 8; j++) {
                    asm volatile(
                        "mma.sync.aligned.m16n8k16.row.col.f32.f16.f16.f32 "
                        "{%0,%1,%2,%3}, {%4,%5,%6,%7}, {%8,%9}, {%0,%1,%2,%3};"
                        : "+f"(acc[i][j][0]), "+f"(acc[i][j][1]),
                          "+f"(acc[i][j][2]), "+f"(acc[i][j][3])
                        : "r"(af[i][0]), "r"(af[i][1]), "r"(af[i][2]), "r"(af[i][3]),
                          "r"(bf[j][0]), "r"(bf[j][1]));
                }
        }
        __syncthreads();

        if (kt < 31) {
#pragma unroll
            for (int q = 0; q < 4; q++) {
                sA[s ^ 1][akp + 2 * q + 0][am] = packh2(ra[q].x, ra[q].y);
                sA[s ^ 1][akp + 2 * q + 1][am] = packh2(ra[q].z, ra[q].w);
            }
        }
    }

    // epilogue: tanh + w-weighted column reduce for this 128-col tile
    float sprt[4] = {0.f, 0.f, 0.f, 0.f};
#pragma unroll
    for (int i = 0; i < 2; i++)
#pragma unroll
        for (int j = 0; j < 8; j++) {
            const int c0 = wn * 64 + j * 8 + 2 * tig;
            const float d0 = sdec[c0], d1 = sdec[c0 + 1];
            const float w0 = swv[c0],  w1 = swv[c0 + 1];
            sprt[2 * i + 0] += w0 * tanhfast(acc[i][j][0] + d0) + w1 * tanhfast(acc[i][j][1] + d1);
            sprt[2 * i + 1] += w0 * tanhfast(acc[i][j][2] + d0) + w1 * tanhfast(acc[i][j][3] + d1);
        }

#pragma unroll
    for (int off = 2; off; off >>= 1)
#pragma unroll
        for (int r = 0; r < 4; r++)
            sprt[r] += __shfl_down_sync(0xffffffffu, sprt[r], off, 4);

    if (tig == 0) {
#pragma unroll
        for (int r = 0; r < 4; r++)
            sred[wm * 32 + g + 8 * r][wn] = sprt[r];
    }
    __syncthreads();
    if (tid < BM)
        g_scp[ntb][m0 + tid] = sred[tid][0] + sred[tid][1];
}

// ---------------------------------------------------------------------------
// Kernel 3: sum partials + masked softmax over S per batch row. grid NB.
// ---------------------------------------------------------------------------
__global__ void __launch_bounds__(256) k_softmax(const int* __restrict__ enc_len,
                                                 float* __restrict__ attn_out) {
    __shared__ float ssc[SL];
    __shared__ float red[256];
    int b = blockIdx.x;
    int len = enc_len[b];
    int t = threadIdx.x;

    for (int s = t; s < SL; s += 256) {
        float v = 0.f;
#pragma unroll
        for (int p = 0; p < NT_TILES; p++) v += g_scp[p][b * SL + s];
        ssc[s] = v;
    }
    __syncthreads();

    float m = -1e30f;
    for (int s = t; s < len; s += 256) m = fmaxf(m, ssc[s]);
    red[t] = m;
    __syncthreads();
    for (int o = 128; o; o >>= 1) {
        if (t < o) red[t] = fmaxf(red[t], red[t + o]);
        __syncthreads();
    }
    m = red[0];
    __syncthreads();

    float sum = 0.f;
    for (int s = t; s < len; s += 256) sum += expf(ssc[s] - m);
    red[t] = sum;
    __syncthreads();
    for (int o = 128; o; o >>= 1) {
        if (t < o) red[t] += red[t + o];
        __syncthreads();
    }
    float inv = 1.f / red[0];

    for (int s = t; s < SL; s += 256)
        attn_out[b * SL + s] = (s < len) ? expf(ssc[s] - m) * inv : 0.f;
}

// ---------------------------------------------------------------------------
// Kernel 4: context partials. attn is exactly 0 beyond len, so no masking.
// ---------------------------------------------------------------------------
__global__ void __launch_bounds__(256) k_context(const float* __restrict__ enc,
                                                 const float* __restrict__ attn) {
    __shared__ float sat[CS];
    int b = blockIdx.y, ch = blockIdx.z;
    int e = blockIdx.x * 256 + threadIdx.x;
    int s0 = ch * CS;

    for (int i = threadIdx.x; i < CS; i += 256) sat[i] = attn[b * SL + s0 + i];
    __syncthreads();

    const float* eb = enc + ((size_t)b * SL + s0) * ENC_D + e;
    float a0 = 0.f, a1 = 0.f, a2 = 0.f, a3 = 0.f;
#pragma unroll 4
    for (int s = 0; s < CS; s += 4) {
        a0 += sat[s + 0] * eb[(size_t)(s + 0) * ENC_D];
        a1 += sat[s + 1] * eb[(size_t)(s + 1) * ENC_D];
        a2 += sat[s + 2] * eb[(size_t)(s + 2) * ENC_D];
        a3 += sat[s + 3] * eb[(size_t)(s + 3) * ENC_D];
    }
    g_ctxp[ch][b * ENC_D + e] = (a0 + a1) + (a2 + a3);
}

// ---------------------------------------------------------------------------
// Kernel 5: out[b][o] = b_out[o] + sum_e (sum_p ctxp[p][b][e]) * W_out[e][o]
// ---------------------------------------------------------------------------
__global__ void __launch_bounds__(256) k_out(const float* __restrict__ Wo,
                                             const float* __restrict__ bo,
                                             float* __restrict__ out) {
    __shared__ float sctx[1024];
    int b = blockIdx.y;
    for (int i = threadIdx.x; i < 1024; i += 256) {
        float v = 0.f;
#pragma unroll
        for (int p = 0; p < SCH; p++) v += g_ctxp[p][b * ENC_D + i];
        sctx[i] = v;
    }
    __syncthreads();
    int o = blockIdx.x * 256 + threadIdx.x;
    float acc = bo[o];
#pragma unroll 8
    for (int e = 0; e < 1024; e++) acc += sctx[e] * Wo[e * 1024 + o];
    out[b * OUT_D + o] = acc;
}

// ---------------------------------------------------------------------------
extern "C" void kernel_launch(void* const* d_in, const int* in_sizes, int n_in,
                              void* d_out, int out_size) {
    const float* enc     = (const float*)d_in[0];
    const float* dec     = (const float*)d_in[1];
    const float* W_enc   = (const float*)d_in[2];
    const float* b_enc   = (const float*)d_in[3];
    const float* W_dec   = (const float*)d_in[4];
    const float* b_dec   = (const float*)d_in[5];
    const float* w_attn  = (const float*)d_in[6];
    const float* W_out   = (const float*)d_in[7];
    const float* b_out   = (const float*)d_in[8];
    const int*   enc_len = (const int*)d_in[9];

    float* out      = (float*)d_out;
    float* ctx_out  = out;                 // [NB, OUT_D]
    float* attn_out = out + NB * OUT_D;    // [NB, SL]

    k_prep<<<(ENC_D / 2) * ATTN_D / 256, 256>>>(W_enc);
    k_dec<<<dim3(ATTN_D / 256, NB), 256>>>(dec, W_dec, b_dec, b_enc);
    k_scores<<<(MROWS / BM) * NT_TILES, 256>>>(enc, w_attn);
    k_softmax<<<NB, 256>>>(enc_len, attn_out);
    k_context<<<dim3(ENC_D / 256, NB, SCH), 256>>>(enc, attn_out);
    k_out<<<dim3(OUT_D / 256, NB), 256>>>(W_out, b_out, ctx_out);
}